// round 6
// baseline (speedup 1.0000x reference)
#include <cuda_runtime.h>

#define N_ 4
#define C_ 256
#define H_ 200
#define W_ 272
#define O_ 7
#define K_CH 20         // h-chunks (parallelism knob)
#define HCH 10          // H_ / K_CH

// Chunk-local 2D integral image, TRANSPOSED layout [n][h][w][c].
__device__ float g_integ[(size_t)N_ * H_ * W_ * C_];
// carry[n][k][w][c] = w-scanned column prefix of all chunks above k.
__device__ float g_carry[(size_t)N_ * K_CH * W_ * C_];

__device__ __forceinline__ float4 f4add(float4 a, float4 b) {
    return make_float4(a.x + b.x, a.y + b.y, a.z + b.z, a.w + b.w);
}
__device__ __forceinline__ float4 f4sub(float4 a, float4 b) {
    return make_float4(a.x - b.x, a.y - b.y, a.z - b.z, a.w - b.w);
}

// --------------------------------------------------------------------------
// Fused H-scan + W-scan + transpose, one pass.
// Block: 96 threads (3 warps), thread = 4 consecutive w (68 active).
// Block owns (n, h-chunk k, 8 channels), HCH rows each.
// Grid: (32, 20, 4) = 2560 blocks. launch_bounds caps regs so occupancy
// is register-feasible at ~10 blocks/SM (30 warps).
// --------------------------------------------------------------------------
__global__ __launch_bounds__(96, 10) void fused_scan(const float* __restrict__ fm) {
    __shared__ float wsum[2][8][4];   // [buf][channel][warp], 3 warps used

    const int c0 = blockIdx.x * 8;
    const int k  = blockIdx.y;
    const int n  = blockIdx.z;
    const int slot = threadIdx.x;     // 0..95, active < 68
    const int lane = slot & 31;
    const int wid  = slot >> 5;       // 0..2
    const bool active = (slot < 68);
    const int w0 = slot * 4;

    float acc[8][4];
    #pragma unroll
    for (int j = 0; j < 8; ++j)
        #pragma unroll
        for (int e = 0; e < 4; ++e) acc[j][e] = 0.f;

    const float4* in0 = (const float4*)(fm + ((size_t)(n * C_ + c0) * H_
                          + (size_t)k * HCH) * W_) + (active ? slot : 0);
    const size_t out_base = (((size_t)n * H_ + (size_t)k * HCH) * W_) * C_ + c0;

    #pragma unroll 2
    for (int lh = 0; lh < HCH; ++lh) {
        const int buf = lh & 1;
        float4 v[8];
        #pragma unroll
        for (int j = 0; j < 8; ++j)
            v[j] = in0[(size_t)j * (H_ * W_ / 4) + lh * (W_ / 4)];

        float sc[8][4];
        #pragma unroll
        for (int j = 0; j < 8; ++j) {
            if (!active) v[j] = make_float4(0.f, 0.f, 0.f, 0.f);
            acc[j][0] += v[j].x;
            acc[j][1] += v[j].y;
            acc[j][2] += v[j].z;
            acc[j][3] += v[j].w;
            const float i0 = acc[j][0];
            const float i1 = i0 + acc[j][1];
            const float i2 = i1 + acc[j][2];
            const float i3 = i2 + acc[j][3];
            float x = i3;                         // warp inclusive scan on totals
            #pragma unroll
            for (int d = 1; d < 32; d <<= 1) {
                float y = __shfl_up_sync(0xffffffff, x, d);
                if (lane >= d) x += y;
            }
            const float excl = x - i3;
            sc[j][0] = i0 + excl;
            sc[j][1] = i1 + excl;
            sc[j][2] = i2 + excl;
            sc[j][3] = i3 + excl;
            if (lane == 31) wsum[buf][j][wid] = x;
        }
        __syncthreads();

        #pragma unroll
        for (int j = 0; j < 8; ++j) {
            float p = 0.f;
            #pragma unroll
            for (int t = 0; t < 2; ++t)
                if (t < wid) p += wsum[buf][j][t];
            #pragma unroll
            for (int e = 0; e < 4; ++e) sc[j][e] += p;
        }

        if (active) {
            float* dst = &g_integ[out_base + ((size_t)lh * W_ + w0) * C_];
            #pragma unroll
            for (int e = 0; e < 4; ++e) {
                float* d = dst + (size_t)e * C_;
                ((float4*)d)[0] = make_float4(sc[0][e], sc[1][e], sc[2][e], sc[3][e]);
                ((float4*)d)[1] = make_float4(sc[4][e], sc[5][e], sc[6][e], sc[7][e]);
            }
        }
    }
}

// --------------------------------------------------------------------------
// carry[n][k][w][c]: exclusive prefix over chunks of each chunk's last row.
// --------------------------------------------------------------------------
__global__ void chunk_carry() {
    const int total = N_ * W_ * C_;
    int idx = blockIdx.x * 256 + threadIdx.x;
    if (idx >= total) return;
    const int c = idx % C_;
    const int w = (idx / C_) % W_;
    const int n = idx / (C_ * W_);

    float p = 0.f;
    #pragma unroll
    for (int k = 0; k < K_CH; ++k) {
        g_carry[(((size_t)n * K_CH + k) * W_ + w) * C_ + c] = p;
        p += g_integ[(((size_t)n * H_ + (size_t)k * HCH + (HCH - 1)) * W_ + w) * C_ + c];
    }
}

// --------------------------------------------------------------------------
// Per-ROI gather. Block per ROI, 256 threads.
// Thread = (channel-quad cq = t&63, bin-group grp = t>>6). Each corner load
// is one float4 (4 channels). Results staged in smem, coalesced writeout.
// --------------------------------------------------------------------------
__global__ void roipool(const int* __restrict__ rois, float* __restrict__ out,
                        int img_off, int R) {
    extern __shared__ float stage[];       // 256 * 49 floats
    __shared__ int sb[4 * O_];             // hs[7] he[7] ws[7] we[7]
    const int r = blockIdx.x;
    if (r >= R) return;
    const int t   = threadIdx.x;
    const int cq  = t & 63;
    const int grp = t >> 6;

    const int n  = rois[r * 5 + 0];
    const int x1 = rois[r * 5 + 1];
    const int y1 = rois[r * 5 + 2];
    const int x2 = rois[r * 5 + 3];
    const int y2 = rois[r * 5 + 4];

    if (t < O_) {
        const int hin = y2 - y1 + 1;
        const int win = x2 - x1 + 1;
        sb[t]          = y1 + (t * hin) / O_;                   // hs
        sb[O_ + t]     = y1 + ((t + 1) * hin + O_ - 1) / O_;    // he
        sb[2 * O_ + t] = x1 + (t * win) / O_;                   // ws
        sb[3 * O_ + t] = x1 + ((t + 1) * win + O_ - 1) / O_;    // we
    }
    __syncthreads();

    const float4* ib = (const float4*)g_integ + (size_t)n * (H_ * W_ * 64) + cq;
    const float4* cb = (const float4*)g_carry + (size_t)n * (K_CH * W_ * 64) + cq;
    const float4 z4 = make_float4(0.f, 0.f, 0.f, 0.f);

    if (img_off > 0 && t == 0) out[r] = (float)n;   // img_idx output

    #pragma unroll
    for (int m = 0; m < 13; ++m) {
        const int b = grp + 4 * m;
        if (b < O_ * O_) {
            const int i = b / O_;
            const int j = b - i * O_;
            const int hiT = sb[i];
            const int hiB = sb[O_ + i];
            const int wL  = sb[2 * O_ + j] - 1;   // may be -1 (pad)
            const int wR  = sb[3 * O_ + j] - 1;
            const int kB  = (hiB - 1) / HCH;
            const int kT  = (hiT > 0) ? (hiT - 1) / HCH : 0;

            float4 BR = f4add(ib[(size_t)((hiB - 1) * W_ + wR) * 64],
                              cb[(size_t)(kB * W_ + wR) * 64]);
            float4 TR = (hiT > 0)
                      ? f4add(ib[(size_t)((hiT - 1) * W_ + wR) * 64],
                              cb[(size_t)(kT * W_ + wR) * 64]) : z4;
            float4 BL = (wL >= 0)
                      ? f4add(ib[(size_t)((hiB - 1) * W_ + wL) * 64],
                              cb[(size_t)(kB * W_ + wL) * 64]) : z4;
            float4 TL = (hiT > 0 && wL >= 0)
                      ? f4add(ib[(size_t)((hiT - 1) * W_ + wL) * 64],
                              cb[(size_t)(kT * W_ + wL) * 64]) : z4;

            const float4 s = f4sub(f4sub(BR, TR), f4sub(BL, TL));
            const float inv = 1.f / ((float)(hiB - hiT) *
                                     (float)(sb[3 * O_ + j] - sb[2 * O_ + j]));
            const int base = (4 * cq) * (O_ * O_) + b;
            stage[base]                 = s.x * inv;
            stage[base + O_ * O_]       = s.y * inv;
            stage[base + 2 * (O_ * O_)] = s.z * inv;
            stage[base + 3 * (O_ * O_)] = s.w * inv;
        }
    }
    __syncthreads();

    // coalesced float4 writeout of the whole tile
    float4* o4 = (float4*)(out + img_off + (size_t)r * (C_ * O_ * O_));
    const float4* s4 = (const float4*)stage;
    const int n4 = C_ * O_ * O_ / 4;   // 3136
    for (int p = t; p < n4; p += 256) o4[p] = s4[p];
}

// --------------------------------------------------------------------------
extern "C" void kernel_launch(void* const* d_in, const int* in_sizes, int n_in,
                              void* d_out, int out_size) {
    const float* fm   = (const float*)d_in[0];
    const int*   rois = (const int*)d_in[1];
    const int R = in_sizes[1] / 5;

    int img_off = out_size - R * C_ * O_ * O_;
    if (img_off < 0) img_off = 0;

    const int smem_bytes = C_ * O_ * O_ * (int)sizeof(float);   // 50176
    cudaFuncSetAttribute(roipool, cudaFuncAttributeMaxDynamicSharedMemorySize,
                         smem_bytes);

    dim3 gF(C_ / 8, K_CH, N_);
    fused_scan<<<gF, 96>>>(fm);

    const int tot = N_ * W_ * C_;
    chunk_carry<<<(tot + 255) / 256, 256>>>();

    roipool<<<R, 256, smem_bytes>>>(rois, (float*)d_out, img_off, R);
}

// round 7
// speedup vs baseline: 1.3033x; 1.3033x over previous
#include <cuda_runtime.h>

#define N_ 4
#define C_ 256
#define H_ 200
#define W_ 272
#define O_ 7
#define K_CH 10         // h-chunks
#define HCH 20          // H_ / K_CH

// Chunk-local 2D integral image, TRANSPOSED layout [n][h][w][c].
__device__ float g_integ[(size_t)N_ * H_ * W_ * C_];
// carry[n][k][w][c] = w-scanned column prefix of all chunks above k.
__device__ float g_carry[(size_t)N_ * K_CH * W_ * C_];

__device__ __forceinline__ float4 f4add(float4 a, float4 b) {
    return make_float4(a.x + b.x, a.y + b.y, a.z + b.z, a.w + b.w);
}
__device__ __forceinline__ float4 f4sub(float4 a, float4 b) {
    return make_float4(a.x - b.x, a.y - b.y, a.z - b.z, a.w - b.w);
}

// --------------------------------------------------------------------------
// Fused H-scan + W-scan + transpose, one pass (R4 structure: runtime row
// loop, no unroll pragma -> compiler software-pipelines loads, regs ~72).
// Block: 96 threads (3 warps), thread = 4 consecutive w (68 active).
// Grid: (32, 10, 4) = 1280 blocks.
// --------------------------------------------------------------------------
__global__ __launch_bounds__(96) void fused_scan(const float* __restrict__ fm) {
    __shared__ float wsum[2][8][4];   // [buf][channel][warp], 3 warps used

    const int c0 = blockIdx.x * 8;
    const int k  = blockIdx.y;
    const int n  = blockIdx.z;
    const int slot = threadIdx.x;     // 0..95, active < 68
    const int lane = slot & 31;
    const int wid  = slot >> 5;       // 0..2
    const bool active = (slot < 68);
    const int w0 = slot * 4;

    float acc[8][4];
    #pragma unroll
    for (int j = 0; j < 8; ++j)
        #pragma unroll
        for (int e = 0; e < 4; ++e) acc[j][e] = 0.f;

    const float4* in0 = (const float4*)(fm + ((size_t)(n * C_ + c0) * H_
                          + (size_t)k * HCH) * W_) + (active ? slot : 0);
    const size_t out_base = (((size_t)n * H_ + (size_t)k * HCH) * W_) * C_ + c0;

    for (int lh = 0; lh < HCH; ++lh) {
        const int buf = lh & 1;
        float4 v[8];
        #pragma unroll
        for (int j = 0; j < 8; ++j)
            v[j] = in0[(size_t)j * (H_ * W_ / 4) + lh * (W_ / 4)];

        float sc[8][4];
        #pragma unroll
        for (int j = 0; j < 8; ++j) {
            if (!active) v[j] = make_float4(0.f, 0.f, 0.f, 0.f);
            acc[j][0] += v[j].x;
            acc[j][1] += v[j].y;
            acc[j][2] += v[j].z;
            acc[j][3] += v[j].w;
            const float i0 = acc[j][0];
            const float i1 = i0 + acc[j][1];
            const float i2 = i1 + acc[j][2];
            const float i3 = i2 + acc[j][3];
            float x = i3;                         // warp inclusive scan on totals
            #pragma unroll
            for (int d = 1; d < 32; d <<= 1) {
                float y = __shfl_up_sync(0xffffffff, x, d);
                if (lane >= d) x += y;
            }
            const float excl = x - i3;
            sc[j][0] = i0 + excl;
            sc[j][1] = i1 + excl;
            sc[j][2] = i2 + excl;
            sc[j][3] = i3 + excl;
            if (lane == 31) wsum[buf][j][wid] = x;
        }
        __syncthreads();

        #pragma unroll
        for (int j = 0; j < 8; ++j) {
            float p = 0.f;
            #pragma unroll
            for (int t = 0; t < 2; ++t)
                if (t < wid) p += wsum[buf][j][t];
            #pragma unroll
            for (int e = 0; e < 4; ++e) sc[j][e] += p;
        }

        if (active) {
            float* dst = &g_integ[out_base + ((size_t)lh * W_ + w0) * C_];
            #pragma unroll
            for (int e = 0; e < 4; ++e) {
                float* d = dst + (size_t)e * C_;
                ((float4*)d)[0] = make_float4(sc[0][e], sc[1][e], sc[2][e], sc[3][e]);
                ((float4*)d)[1] = make_float4(sc[4][e], sc[5][e], sc[6][e], sc[7][e]);
            }
        }
    }
}

// --------------------------------------------------------------------------
// carry[n][k][w][c]: exclusive prefix over chunks of each chunk's last row.
// --------------------------------------------------------------------------
__global__ void chunk_carry() {
    const int total = N_ * W_ * C_;
    int idx = blockIdx.x * 256 + threadIdx.x;
    if (idx >= total) return;
    const int c = idx % C_;
    const int w = (idx / C_) % W_;
    const int n = idx / (C_ * W_);

    float p = 0.f;
    #pragma unroll
    for (int k = 0; k < K_CH; ++k) {
        g_carry[(((size_t)n * K_CH + k) * W_ + w) * C_ + c] = p;
        p += g_integ[(((size_t)n * H_ + (size_t)k * HCH + (HCH - 1)) * W_ + w) * C_ + c];
    }
}

// --------------------------------------------------------------------------
// Per-ROI gather. Block per ROI, 256 threads.
// Thread = (channel-quad cq = t&63, bin-group grp = t>>6).
// Carry terms cancel when both boundary rows share one h-chunk -> skip those
// loads (warp-uniform branch: all lanes of a warp have the same geometry).
// --------------------------------------------------------------------------
__global__ void roipool(const int* __restrict__ rois, float* __restrict__ out,
                        int img_off, int R) {
    extern __shared__ float stage[];       // 256 * 49 floats
    __shared__ int sb[4 * O_];             // hs[7] he[7] ws[7] we[7]
    const int r = blockIdx.x;
    if (r >= R) return;
    const int t   = threadIdx.x;
    const int cq  = t & 63;
    const int grp = t >> 6;

    const int n  = rois[r * 5 + 0];
    const int x1 = rois[r * 5 + 1];
    const int y1 = rois[r * 5 + 2];
    const int x2 = rois[r * 5 + 3];
    const int y2 = rois[r * 5 + 4];

    if (t < O_) {
        const int hin = y2 - y1 + 1;
        const int win = x2 - x1 + 1;
        sb[t]          = y1 + (t * hin) / O_;                   // hs
        sb[O_ + t]     = y1 + ((t + 1) * hin + O_ - 1) / O_;    // he
        sb[2 * O_ + t] = x1 + (t * win) / O_;                   // ws
        sb[3 * O_ + t] = x1 + ((t + 1) * win + O_ - 1) / O_;    // we
    }
    __syncthreads();

    const float4* ib = (const float4*)g_integ + (size_t)n * (H_ * W_ * 64) + cq;
    const float4* cb = (const float4*)g_carry + (size_t)n * (K_CH * W_ * 64) + cq;
    const float4 z4 = make_float4(0.f, 0.f, 0.f, 0.f);

    if (img_off > 0 && t == 0) out[r] = (float)n;   // img_idx output

    #pragma unroll
    for (int m = 0; m < 13; ++m) {
        const int b = grp + 4 * m;
        if (b < O_ * O_) {
            const int i = b / O_;
            const int j = b - i * O_;
            const int hiT = sb[i];
            const int hiB = sb[O_ + i];
            const int wL  = sb[2 * O_ + j] - 1;   // may be -1 (pad)
            const int wR  = sb[3 * O_ + j] - 1;
            const int kB  = (hiB - 1) / HCH;
            const int kT  = (hiT > 0) ? (hiT - 1) / HCH : 0;

            // chunk-local integral corners
            float4 BR = ib[(size_t)((hiB - 1) * W_ + wR) * 64];
            float4 TR = (hiT > 0) ? ib[(size_t)((hiT - 1) * W_ + wR) * 64] : z4;
            float4 BL = (wL >= 0) ? ib[(size_t)((hiB - 1) * W_ + wL) * 64] : z4;
            float4 TL = (hiT > 0 && wL >= 0)
                      ? ib[(size_t)((hiT - 1) * W_ + wL) * 64] : z4;
            float4 s = f4sub(f4sub(BR, TR), f4sub(BL, TL));

            // carry correction; cancels exactly when both rows in one chunk
            // (or top is the zero-pad row and bottom chunk is 0).
            const bool need_carry = (hiT > 0) ? (kB != kT) : (kB != 0);
            if (need_carry) {
                float4 cR = cb[(size_t)(kB * W_ + wR) * 64];
                if (hiT > 0) cR = f4sub(cR, cb[(size_t)(kT * W_ + wR) * 64]);
                float4 cL = z4;
                if (wL >= 0) {
                    cL = cb[(size_t)(kB * W_ + wL) * 64];
                    if (hiT > 0) cL = f4sub(cL, cb[(size_t)(kT * W_ + wL) * 64]);
                }
                s = f4add(s, f4sub(cR, cL));
            }

            const float inv = 1.f / ((float)(hiB - hiT) *
                                     (float)(sb[3 * O_ + j] - sb[2 * O_ + j]));
            const int base = (4 * cq) * (O_ * O_) + b;
            stage[base]                 = s.x * inv;
            stage[base + O_ * O_]       = s.y * inv;
            stage[base + 2 * (O_ * O_)] = s.z * inv;
            stage[base + 3 * (O_ * O_)] = s.w * inv;
        }
    }
    __syncthreads();

    // coalesced float4 writeout of the whole tile
    float4* o4 = (float4*)(out + img_off + (size_t)r * (C_ * O_ * O_));
    const float4* s4 = (const float4*)stage;
    const int n4 = C_ * O_ * O_ / 4;   // 3136
    for (int p = t; p < n4; p += 256) o4[p] = s4[p];
}

// --------------------------------------------------------------------------
extern "C" void kernel_launch(void* const* d_in, const int* in_sizes, int n_in,
                              void* d_out, int out_size) {
    const float* fm   = (const float*)d_in[0];
    const int*   rois = (const int*)d_in[1];
    const int R = in_sizes[1] / 5;

    int img_off = out_size - R * C_ * O_ * O_;
    if (img_off < 0) img_off = 0;

    const int smem_bytes = C_ * O_ * O_ * (int)sizeof(float);   // 50176
    cudaFuncSetAttribute(roipool, cudaFuncAttributeMaxDynamicSharedMemorySize,
                         smem_bytes);

    dim3 gF(C_ / 8, K_CH, N_);
    fused_scan<<<gF, 96>>>(fm);

    const int tot = N_ * W_ * C_;
    chunk_carry<<<(tot + 255) / 256, 256>>>();

    roipool<<<R, 256, smem_bytes>>>(rois, (float*)d_out, img_off, R);
}